// round 14
// baseline (speedup 1.0000x reference)
#include <cuda_runtime.h>
#include <cuda_bf16.h>
#include <cstdint>

// Problem constants
#define EMBED 2048
#define NHEAD 16
#define HDIM  128
#define BATCH 2
#define SEQ   2048
#define NTOK  (BATCH * SEQ)   // 4096

__device__ __constant__ float kScale = 0.022097086912079612f;  // 2048^-0.5

// ---------------------------------------------------------------------------
// Static device scratch (allocation-free per harness rules)
// ---------------------------------------------------------------------------
__device__ __nv_bfloat16 g_Xh[(size_t)NTOK * EMBED];             // x hi/lo
__device__ __nv_bfloat16 g_Xl[(size_t)NTOK * EMBED];
__device__ __nv_bfloat16 g_Ah[(size_t)NTOK * EMBED];             // attn-out hi/lo
__device__ __nv_bfloat16 g_Al[(size_t)NTOK * EMBED];
__device__ __nv_bfloat16 g_Wh[4][(size_t)EMBED * EMBED];         // W^T hi/lo: [n][k]
__device__ __nv_bfloat16 g_Wl[4][(size_t)EMBED * EMBED];
// QKV in bf16 hi/lo, [bh][t][hd]; Q pre-scaled by kScale
__device__ __nv_bfloat16 g_Qh[(size_t)BATCH * NHEAD * SEQ * HDIM];
__device__ __nv_bfloat16 g_Ql[(size_t)BATCH * NHEAD * SEQ * HDIM];
__device__ __nv_bfloat16 g_Kh[(size_t)BATCH * NHEAD * SEQ * HDIM];
__device__ __nv_bfloat16 g_Kl[(size_t)BATCH * NHEAD * SEQ * HDIM];
__device__ __nv_bfloat16 g_Vh[(size_t)BATCH * NHEAD * SEQ * HDIM];
__device__ __nv_bfloat16 g_Vl[(size_t)BATCH * NHEAD * SEQ * HDIM];

// ---------------------------------------------------------------------------
// sm_80-era PTX helpers (base-target ISA; no 'a' features — R11 constraint)
// ---------------------------------------------------------------------------
__device__ __forceinline__ uint32_t smem_u32(const void* p) {
    uint32_t a;
    asm("{ .reg .u64 t; cvta.to.shared.u64 t, %1; cvt.u32.u64 %0, t; }"
        : "=r"(a) : "l"(p));
    return a;
}

__device__ __forceinline__ void ldsm4(uint32_t* r, uint32_t addr) {
    asm volatile("ldmatrix.sync.aligned.m8n8.x4.shared.b16 {%0,%1,%2,%3}, [%4];"
                 : "=r"(r[0]), "=r"(r[1]), "=r"(r[2]), "=r"(r[3]) : "r"(addr));
}
__device__ __forceinline__ void ldsm4t(uint32_t* r, uint32_t addr) {
    asm volatile("ldmatrix.sync.aligned.m8n8.x4.trans.shared.b16 {%0,%1,%2,%3}, [%4];"
                 : "=r"(r[0]), "=r"(r[1]), "=r"(r[2]), "=r"(r[3]) : "r"(addr));
}

__device__ __forceinline__ void mma_bf16(float* c, const uint32_t* a,
                                         const uint32_t* b) {
    asm volatile(
        "mma.sync.aligned.m16n8k16.row.col.f32.bf16.bf16.f32 "
        "{%0,%1,%2,%3}, {%4,%5,%6,%7}, {%8,%9}, {%0,%1,%2,%3};"
        : "+f"(c[0]), "+f"(c[1]), "+f"(c[2]), "+f"(c[3])
        : "r"(a[0]), "r"(a[1]), "r"(a[2]), "r"(a[3]), "r"(b[0]), "r"(b[1]));
}

__device__ __forceinline__ void cp16(uint32_t sdst, const void* gsrc) {
    asm volatile("cp.async.cg.shared.global [%0], [%1], 16;"
                 :: "r"(sdst), "l"(gsrc) : "memory");
}
#define CP_COMMIT asm volatile("cp.async.commit_group;" ::: "memory")
#define CP_WAIT0  asm volatile("cp.async.wait_group 0;" ::: "memory")
#define CP_WAIT1  asm volatile("cp.async.wait_group 1;" ::: "memory")
#define CP_WAIT2  asm volatile("cp.async.wait_group 2;" ::: "memory")

// Swizzle for 256B-pitch bf16 tiles: 16B chunk c of row r -> c XOR (r&7) in low 3 bits
__device__ __forceinline__ uint32_t swz(uint32_t row, uint32_t byte) {
    uint32_t c = byte >> 4;
    return row * 256 + ((((c ^ row) & 7u) | (c & 8u)) << 4) + (byte & 15u);
}

__device__ __forceinline__ void bf16_split(float v, __nv_bfloat16& h, __nv_bfloat16& l) {
    h = __float2bfloat16_rn(v);
    l = __float2bfloat16_rn(v - __bfloat162float(h));
}
// split (a,b) -> packed hi bf16x2, lo bf16x2 (low half = first element)
__device__ __forceinline__ void split_pack2(float a, float b, uint32_t& h, uint32_t& l) {
    __nv_bfloat16 ha, la, hb, lb;
    bf16_split(a, ha, la); bf16_split(b, hb, lb);
    __nv_bfloat162 H = __halves2bfloat162(ha, hb);
    __nv_bfloat162 L = __halves2bfloat162(la, lb);
    h = *reinterpret_cast<uint32_t*>(&H);
    l = *reinterpret_cast<uint32_t*>(&L);
}

// ---------------------------------------------------------------------------
// Prep kernels
// ---------------------------------------------------------------------------
__global__ void split_kernel(const float* __restrict__ src) {
    size_t i = (size_t)blockIdx.x * blockDim.x + threadIdx.x;  // float4 index
    float4 v = ((const float4*)src)[i];
    uint32_t h0, l0, h1, l1;
    split_pack2(v.x, v.y, h0, l0);
    split_pack2(v.z, v.w, h1, l1);
    ((uint32_t*)g_Xh)[i * 2 + 0] = h0; ((uint32_t*)g_Xh)[i * 2 + 1] = h1;
    ((uint32_t*)g_Xl)[i * 2 + 0] = l0; ((uint32_t*)g_Xl)[i * 2 + 1] = l1;
}

// Transpose + split: w[k][n] fp32 -> g_Wh/g_Wl[z][n][k] bf16
__global__ void wsplit_kernel(const float* __restrict__ wq,
                              const float* __restrict__ wk,
                              const float* __restrict__ wv,
                              const float* __restrict__ wo) {
    __shared__ float tile[32][33];
    const int z = blockIdx.z;
    const float* w = (z == 0) ? wq : (z == 1) ? wk : (z == 2) ? wv : wo;
    const int n0 = blockIdx.x * 32, k0 = blockIdx.y * 32;
    const int tx = threadIdx.x, ty = threadIdx.y;  // 32 x 8
#pragma unroll
    for (int i = 0; i < 4; i++)
        tile[ty + 8 * i][tx] = w[(size_t)(k0 + ty + 8 * i) * EMBED + n0 + tx];
    __syncthreads();
#pragma unroll
    for (int i = 0; i < 4; i++) {
        float v = tile[tx][ty + 8 * i];
        __nv_bfloat16 h, l;
        bf16_split(v, h, l);
        size_t off = (size_t)(n0 + ty + 8 * i) * EMBED + k0 + tx;
        g_Wh[z][off] = h;
        g_Wl[z][off] = l;
    }
}

// ---------------------------------------------------------------------------
// mma.sync GEMM: C = A @ W^T + bias, bf16 hi/lo 3-pass, fp32 acc.
// CTA 128x128, 8 warps (64x32 warp tiles), k-chunk 32.
// cp.async 4-stage pipeline (3 in flight), one __syncthreads per chunk.
// 80B row pitch -> conflict-free ldmatrix phases.
// mode 0: fp32 row-major out.  mode 1: (acc+bias)*scale, split hi/lo,
//         scatter to [bh][t][hd] bf16 arrays (one head per blockIdx.x).
// ---------------------------------------------------------------------------
#define PITCH_B   80
#define ASZ       (128 * PITCH_B)      // 10240 B per array
#define STAGE_B   (4 * ASZ)            // Ah, Al, Bh, Bl = 40960 B
#define NSTAGE    4
#define GEMM_SMEM (NSTAGE * STAGE_B)   // 163840 B
#define NCHUNK    (EMBED / 32)         // 64

__device__ __forceinline__ void mma_gemm_body(
    const __nv_bfloat16* __restrict__ Ah, const __nv_bfloat16* __restrict__ Al,
    const __nv_bfloat16* __restrict__ Bh, const __nv_bfloat16* __restrict__ Bl,
    const float* __restrict__ bias, float* __restrict__ outp,
    int mode, int head, __nv_bfloat16* outh, __nv_bfloat16* outl, float scale)
{
    extern __shared__ char smem[];
    const uint32_t sbase = smem_u32(smem);

    const int tid  = threadIdx.x;
    const int wid  = tid >> 5, lane = tid & 31;
    const int m0   = blockIdx.y * 128;
    const int n0   = blockIdx.x * 128;

    // Loader mapping: thread -> row (tid>>1), 16B chunk pair (tid&1)*2 + {0,1}
    const int lrow = tid >> 1;
    const int lc0  = (tid & 1) * 2;
    const char* gAh = (const char*)(Ah + (size_t)(m0 + lrow) * EMBED);
    const char* gAl = (const char*)(Al + (size_t)(m0 + lrow) * EMBED);
    const char* gBh = (const char*)(Bh + (size_t)(n0 + lrow) * EMBED);
    const char* gBl = (const char*)(Bl + (size_t)(n0 + lrow) * EMBED);
    const uint32_t sro = (uint32_t)lrow * PITCH_B + lc0 * 16;

    auto load_stage = [&](int stage, int c) {
        const uint32_t s = sbase + stage * STAGE_B + sro;
        const size_t ko = (size_t)c * 64 + lc0 * 16;
#pragma unroll
        for (int i = 0; i < 2; i++) {
            cp16(s + i * 16,           gAh + ko + i * 16);
            cp16(s + ASZ + i * 16,     gAl + ko + i * 16);
            cp16(s + 2 * ASZ + i * 16, gBh + ko + i * 16);
            cp16(s + 3 * ASZ + i * 16, gBl + ko + i * 16);
        }
    };

    float acc[4][4][4];
#pragma unroll
    for (int i = 0; i < 4; i++)
#pragma unroll
        for (int j = 0; j < 4; j++)
#pragma unroll
            for (int r = 0; r < 4; r++) acc[i][j][r] = 0.0f;

    const int wm = (wid & 1) * 64;
    const int wn = (wid >> 1) * 32;
    const uint32_t arow = lane & 15;
    const uint32_t akh  = lane >> 4;
    const uint32_t bn   = (lane & 7) + ((lane >> 4) & 1) * 8;
    const uint32_t bkh  = (lane >> 3) & 1;

    auto compute = [&](int stage) {
        const uint32_t s = sbase + stage * STAGE_B;
#pragma unroll
        for (int ks = 0; ks < 2; ks++) {
            uint32_t ah[4][4], al[4][4];
#pragma unroll
            for (int mi = 0; mi < 4; mi++) {
                const uint32_t ad = s + (wm + mi * 16 + arow) * PITCH_B
                                      + ks * 32 + akh * 16;
                ldsm4(ah[mi], ad);
                ldsm4(al[mi], ad + ASZ);
            }
            uint32_t bh[2][4], bl[2][4];
#pragma unroll
            for (int jj = 0; jj < 2; jj++) {
                const uint32_t bd = s + 2 * ASZ + (wn + jj * 16 + bn) * PITCH_B
                                      + ks * 32 + bkh * 16;
                ldsm4(bh[jj], bd);
                ldsm4(bl[jj], bd + ASZ);
            }
#pragma unroll
            for (int mi = 0; mi < 4; mi++)
#pragma unroll
                for (int nj = 0; nj < 4; nj++) {
                    const uint32_t* bhp = &bh[nj >> 1][(nj & 1) * 2];
                    const uint32_t* blp = &bl[nj >> 1][(nj & 1) * 2];
                    mma_bf16(acc[mi][nj], ah[mi], bhp);
                    mma_bf16(acc[mi][nj], ah[mi], blp);
                    mma_bf16(acc[mi][nj], al[mi], bhp);
                }
        }
    };

    // 4-stage cp.async pipeline, 3 loads in flight
    load_stage(0, 0); CP_COMMIT;
    load_stage(1, 1); CP_COMMIT;
    load_stage(2, 2); CP_COMMIT;
    for (int c = 0; c < NCHUNK; c++) {
        CP_WAIT2;              // stage c's group complete (per-thread)
        __syncthreads();       // all threads' groups complete
        if (c + 3 < NCHUNK) load_stage((c + 3) & 3, c + 3);
        CP_COMMIT;             // keep group accounting uniform (empty ok)
        compute(c & 3);
    }

    const int r0 = lane >> 2, c0 = (lane & 3) * 2;
#pragma unroll
    for (int mi = 0; mi < 4; mi++) {
#pragma unroll
        for (int ro = 0; ro < 2; ro++) {
            const int m = m0 + wm + mi * 16 + r0 + ro * 8;
            if (mode == 0) {
                float* dst = outp + (size_t)m * EMBED + n0;
#pragma unroll
                for (int nj = 0; nj < 4; nj++) {
                    const int nl = wn + nj * 8 + c0;
                    float2 v;
                    v.x = acc[mi][nj][ro * 2 + 0] + __ldg(&bias[n0 + nl]);
                    v.y = acc[mi][nj][ro * 2 + 1] + __ldg(&bias[n0 + nl + 1]);
                    *(float2*)(dst + nl) = v;
                }
            } else {
                const int b = m >> 11, t = m & 2047;
                const size_t base = ((size_t)(b * NHEAD + head) * SEQ + t) * HDIM;
#pragma unroll
                for (int nj = 0; nj < 4; nj++) {
                    const int nl = wn + nj * 8 + c0;
                    float vx = (acc[mi][nj][ro * 2 + 0] + __ldg(&bias[n0 + nl])) * scale;
                    float vy = (acc[mi][nj][ro * 2 + 1] + __ldg(&bias[n0 + nl + 1])) * scale;
                    uint32_t h, l;
                    split_pack2(vx, vy, h, l);
                    *(uint32_t*)(outh + base + nl) = h;
                    *(uint32_t*)(outl + base + nl) = l;
                }
            }
        }
    }
}

__global__ __launch_bounds__(256, 1) void qkv_mma_kernel(
    const float* bq, const float* bk, const float* bv)
{
    const int z = blockIdx.z;
    const float* bias = (z == 0) ? bq : (z == 1) ? bk : bv;
    __nv_bfloat16* oh = (z == 0) ? g_Qh : (z == 1) ? g_Kh : g_Vh;
    __nv_bfloat16* ol = (z == 0) ? g_Ql : (z == 1) ? g_Kl : g_Vl;
    const float sc = (z == 0) ? kScale : 1.0f;
    mma_gemm_body(g_Xh, g_Xl, g_Wh[z], g_Wl[z], bias, nullptr, 1, blockIdx.x,
                  oh, ol, sc);
}

__global__ __launch_bounds__(256, 1) void o_mma_kernel(
    const float* bo, float* out)
{
    mma_gemm_body(g_Ah, g_Al, g_Wh[3], g_Wl[3], bo, out, 0, 0,
                  nullptr, nullptr, 1.0f);
}

// ---------------------------------------------------------------------------
// FA2 attention on tensor cores. 256 threads (8 warps), 128 q-rows per CTA,
// 64-key tiles, cp.async double-buffered K/V, hi/lo split throughout.
// Q tile stays RESIDENT in smem (hi+lo); Q fragments re-loaded via ldmatrix
// per k-slice to keep register count low (R13: 255 regs -> spills).
// Smem: Q 64KB + 2 stages x 64KB K/V = 192KB.
// ---------------------------------------------------------------------------
#define KV_TILE_B  (64 * 256)          // 16 KB per 64x128 bf16 tile
#define AT_STAGE   (4 * KV_TILE_B)     // Kh, Kl, Vh, Vl
#define AT_Q_B     (2 * 32768)         // Qh + Ql
#define AT_SMEM    (AT_Q_B + 2 * AT_STAGE)   // 196608 B
#define NKT        (SEQ / 64)          // 32

__global__ __launch_bounds__(256, 1) void attn_mma_kernel()
{
    extern __shared__ char smem[];
    const uint32_t sb  = smem_u32(smem);          // Qh
    const uint32_t sbl = sb + 32768;              // Ql
    const uint32_t skv = sb + AT_Q_B;             // K/V stages
    const int tid = threadIdx.x, lane = tid & 31, wid = tid >> 5;
    const int bh = blockIdx.y;
    const int q0 = blockIdx.x * 128;
    const size_t bho = (size_t)bh * SEQ * HDIM;

    const char* gKh = (const char*)(g_Kh + bho);
    const char* gKl = (const char*)(g_Kl + bho);
    const char* gVh = (const char*)(g_Vh + bho);
    const char* gVl = (const char*)(g_Vl + bho);

    auto load_stage = [&](int stage, int kt) {
        const uint32_t s = skv + stage * AT_STAGE;
        const int row = tid >> 2;
        const size_t go = (size_t)(kt * 64 + row) * 256;   // bytes
#pragma unroll
        for (int i = 0; i < 4; i++) {
            const uint32_t c = (tid & 3) * 4 + i;
            const uint32_t so = swz(row, c * 16);
            cp16(s + so,                  gKh + go + c * 16);
            cp16(s + KV_TILE_B + so,      gKl + go + c * 16);
            cp16(s + 2 * KV_TILE_B + so,  gVh + go + c * 16);
            cp16(s + 3 * KV_TILE_B + so,  gVl + go + c * 16);
        }
    };

    // ---- Async-load Q tile (resident) + K/V stage 0 ----
    {
        const int row = tid >> 1;
        const char* gqh = (const char*)(g_Qh + bho + (size_t)(q0 + row) * HDIM);
        const char* gql = (const char*)(g_Ql + bho + (size_t)(q0 + row) * HDIM);
#pragma unroll
        for (int i = 0; i < 8; i++) {
            const uint32_t c = (tid & 1) * 8 + i;
            const uint32_t so = swz(row, c * 16);
            cp16(sb + so,  gqh + c * 16);
            cp16(sbl + so, gql + c * 16);
        }
        CP_COMMIT;
    }
    load_stage(0, 0); CP_COMMIT;

    // ---- Online-softmax state + O accumulators ----
    float oacc[16][4];
#pragma unroll
    for (int j = 0; j < 16; j++)
#pragma unroll
        for (int r = 0; r < 4; r++) oacc[j][r] = 0.0f;
    float mrow[2] = {-1e30f, -1e30f}, lrow[2] = {0.0f, 0.0f};

    const uint32_t qrow     = wid * 16 + (lane & 15);
    const uint32_t qkh      = (lane >> 4) * 16;
    const uint32_t krow_off = (lane & 7) + ((lane >> 4) & 1) * 8;  // S-phase
    const uint32_t kb_off   = ((lane >> 3) & 1) * 16;
    const uint32_t vrow_off = (lane & 7) + ((lane >> 3) & 1) * 8;  // PV-phase
    const uint32_t vb_off   = ((lane >> 4) & 1) * 16;

    for (int kt = 0; kt < NKT; kt++) {
        if (kt + 1 < NKT) { load_stage((kt + 1) & 1, kt + 1); CP_COMMIT; CP_WAIT1; }
        else              { CP_WAIT0; }
        __syncthreads();

        const uint32_t s = skv + (kt & 1) * AT_STAGE;

        // ---- S = Q K^T (3-pass hi/lo), fp32 acc; Q frags from resident smem ----
        float sacc[8][4];
#pragma unroll
        for (int j = 0; j < 8; j++)
#pragma unroll
            for (int r = 0; r < 4; r++) sacc[j][r] = 0.0f;

#pragma unroll
        for (int ks = 0; ks < 8; ks++) {
            uint32_t qh[4], ql[4];
            {
                const uint32_t so = swz(qrow, ks * 32 + qkh);
                ldsm4(qh, sb + so);
                ldsm4(ql, sbl + so);
            }
            uint32_t kbh[4][4], kbl[4][4];
#pragma unroll
            for (int jp = 0; jp < 4; jp++) {
                const uint32_t so = swz(jp * 16 + krow_off, ks * 32 + kb_off);
                ldsm4(kbh[jp], s + so);
                ldsm4(kbl[jp], s + KV_TILE_B + so);
            }
#pragma unroll
            for (int jp = 0; jp < 4; jp++) {
                mma_bf16(sacc[2*jp],   qh, &kbh[jp][0]);
                mma_bf16(sacc[2*jp],   qh, &kbl[jp][0]);
                mma_bf16(sacc[2*jp],   ql, &kbh[jp][0]);
                mma_bf16(sacc[2*jp+1], qh, &kbh[jp][2]);
                mma_bf16(sacc[2*jp+1], qh, &kbl[jp][2]);
                mma_bf16(sacc[2*jp+1], ql, &kbh[jp][2]);
            }
        }

        // ---- Online softmax (rows lane>>2 and lane>>2+8) ----
#pragma unroll
        for (int rr = 0; rr < 2; rr++) {
            float mt = -1e30f;
#pragma unroll
            for (int j = 0; j < 8; j++)
                mt = fmaxf(mt, fmaxf(sacc[j][rr*2], sacc[j][rr*2+1]));
            mt = fmaxf(mt, __shfl_xor_sync(0xffffffffu, mt, 1));
            mt = fmaxf(mt, __shfl_xor_sync(0xffffffffu, mt, 2));
            const float mn = fmaxf(mrow[rr], mt);
            const float alpha = __expf(mrow[rr] - mn);
            float ls = 0.0f;
#pragma unroll
            for (int j = 0; j < 8; j++) {
                float p0 = __expf(sacc[j][rr*2]   - mn);
                float p1 = __expf(sacc[j][rr*2+1] - mn);
                sacc[j][rr*2] = p0; sacc[j][rr*2+1] = p1;
                ls += p0 + p1;
            }
            ls += __shfl_xor_sync(0xffffffffu, ls, 1);
            ls += __shfl_xor_sync(0xffffffffu, ls, 2);
            lrow[rr] = lrow[rr] * alpha + ls;
            mrow[rr] = mn;
#pragma unroll
            for (int j = 0; j < 16; j++) {
                oacc[j][rr*2]   *= alpha;
                oacc[j][rr*2+1] *= alpha;
            }
        }

        // ---- O += P V (3-pass hi/lo), P packed in-register from sacc ----
#pragma unroll
        for (int ks = 0; ks < 4; ks++) {
            uint32_t pah[4], pal[4];
#pragma unroll
            for (int half = 0; half < 2; half++) {
                const float* sc = sacc[2*ks + half];
                split_pack2(sc[0], sc[1], pah[2*half],   pal[2*half]);
                split_pack2(sc[2], sc[3], pah[2*half+1], pal[2*half+1]);
            }
#pragma unroll
            for (int jp = 0; jp < 8; jp++) {
                uint32_t vbh[4], vbl[4];
                const uint32_t so = swz(ks * 16 + vrow_off, jp * 32 + vb_off);
                ldsm4t(vbh, s + 2 * KV_TILE_B + so);
                ldsm4t(vbl, s + 3 * KV_TILE_B + so);
                mma_bf16(oacc[2*jp],   pah, &vbh[0]);
                mma_bf16(oacc[2*jp],   pah, &vbl[0]);
                mma_bf16(oacc[2*jp],   pal, &vbh[0]);
                mma_bf16(oacc[2*jp+1], pah, &vbh[2]);
                mma_bf16(oacc[2*jp+1], pah, &vbl[2]);
                mma_bf16(oacc[2*jp+1], pal, &vbh[2]);
            }
        }
        __syncthreads();
    }

    // ---- Epilogue: normalize, split hi/lo, write [b,t,h*128+hd] ----
    const int b_ = bh >> 4, h_ = bh & 15;
    const float inv0 = 1.0f / lrow[0], inv1 = 1.0f / lrow[1];
#pragma unroll
    for (int rr = 0; rr < 2; rr++) {
        const int t = q0 + wid * 16 + (lane >> 2) + rr * 8;
        const size_t base = ((size_t)(b_ * SEQ + t)) * EMBED + h_ * HDIM;
        const float inv = rr ? inv1 : inv0;
#pragma unroll
        for (int j = 0; j < 16; j++) {
            const int hd = j * 8 + (lane & 3) * 2;
            uint32_t h, l;
            split_pack2(oacc[j][rr*2] * inv, oacc[j][rr*2+1] * inv, h, l);
            *(uint32_t*)(g_Ah + base + hd) = h;
            *(uint32_t*)(g_Al + base + hd) = l;
        }
    }
}

// ---------------------------------------------------------------------------
// Launch sequence
// ---------------------------------------------------------------------------
extern "C" void kernel_launch(void* const* d_in, const int* in_sizes, int n_in,
                              void* d_out, int out_size)
{
    (void)in_sizes; (void)n_in; (void)out_size;
    const float* x  = (const float*)d_in[0];
    const float* wq = (const float*)d_in[1];
    const float* bq = (const float*)d_in[2];
    const float* wk = (const float*)d_in[3];
    const float* bk = (const float*)d_in[4];
    const float* wv = (const float*)d_in[5];
    const float* bv = (const float*)d_in[6];
    const float* wo = (const float*)d_in[7];
    const float* bo = (const float*)d_in[8];
    float* out = (float*)d_out;

    cudaFuncSetAttribute(qkv_mma_kernel,
                         cudaFuncAttributeMaxDynamicSharedMemorySize, GEMM_SMEM);
    cudaFuncSetAttribute(o_mma_kernel,
                         cudaFuncAttributeMaxDynamicSharedMemorySize, GEMM_SMEM);
    cudaFuncSetAttribute(attn_mma_kernel,
                         cudaFuncAttributeMaxDynamicSharedMemorySize, AT_SMEM);

    // 1. split x -> bf16 hi/lo
    split_kernel<<<(NTOK * EMBED / 4) / 256, 256>>>(x);
    // 2. transpose + split all four weight matrices
    wsplit_kernel<<<dim3(EMBED / 32, EMBED / 32, 4), dim3(32, 8)>>>(wq, wk, wv, wo);
    // 3. QKV projections -> bf16 hi/lo QKV (Q pre-scaled)
    qkv_mma_kernel<<<dim3(16, 32, 3), 256, GEMM_SMEM>>>(bq, bk, bv);
    // 4. tensor-core flash attention -> bf16 hi/lo A
    attn_mma_kernel<<<dim3(SEQ / 128, BATCH * NHEAD), 256, AT_SMEM>>>();
    // 5. output projection -> fp32 out
    o_mma_kernel<<<dim3(16, 32, 1), 256, GEMM_SMEM>>>(bo, out);
}

// round 15
// speedup vs baseline: 1.4080x; 1.4080x over previous
#include <cuda_runtime.h>
#include <cuda_bf16.h>
#include <cstdint>

// Problem constants
#define EMBED 2048
#define NHEAD 16
#define HDIM  128
#define BATCH 2
#define SEQ   2048
#define NTOK  (BATCH * SEQ)   // 4096

__device__ __constant__ float kScale = 0.022097086912079612f;  // 2048^-0.5

// ---------------------------------------------------------------------------
// Static device scratch (allocation-free per harness rules)
// ---------------------------------------------------------------------------
__device__ __nv_bfloat16 g_Xh[(size_t)NTOK * EMBED];             // x hi/lo
__device__ __nv_bfloat16 g_Xl[(size_t)NTOK * EMBED];
__device__ __nv_bfloat16 g_Ah[(size_t)NTOK * EMBED];             // attn-out hi/lo
__device__ __nv_bfloat16 g_Al[(size_t)NTOK * EMBED];
__device__ __nv_bfloat16 g_Wh[4][(size_t)EMBED * EMBED];         // W^T hi/lo: [n][k]
__device__ __nv_bfloat16 g_Wl[4][(size_t)EMBED * EMBED];
// QKV [bh][t][hd]; Q (pre-scaled) and K single bf16; V hi/lo
__device__ __nv_bfloat16 g_Qh[(size_t)BATCH * NHEAD * SEQ * HDIM];
__device__ __nv_bfloat16 g_Kh[(size_t)BATCH * NHEAD * SEQ * HDIM];
__device__ __nv_bfloat16 g_Vh[(size_t)BATCH * NHEAD * SEQ * HDIM];
__device__ __nv_bfloat16 g_Vl[(size_t)BATCH * NHEAD * SEQ * HDIM];

// ---------------------------------------------------------------------------
// sm_80-era PTX helpers (base-target ISA; no 'a' features — R11 constraint)
// ---------------------------------------------------------------------------
__device__ __forceinline__ uint32_t smem_u32(const void* p) {
    uint32_t a;
    asm("{ .reg .u64 t; cvta.to.shared.u64 t, %1; cvt.u32.u64 %0, t; }"
        : "=r"(a) : "l"(p));
    return a;
}

__device__ __forceinline__ void ldsm4(uint32_t* r, uint32_t addr) {
    asm volatile("ldmatrix.sync.aligned.m8n8.x4.shared.b16 {%0,%1,%2,%3}, [%4];"
                 : "=r"(r[0]), "=r"(r[1]), "=r"(r[2]), "=r"(r[3]) : "r"(addr));
}
__device__ __forceinline__ void ldsm4t(uint32_t* r, uint32_t addr) {
    asm volatile("ldmatrix.sync.aligned.m8n8.x4.trans.shared.b16 {%0,%1,%2,%3}, [%4];"
                 : "=r"(r[0]), "=r"(r[1]), "=r"(r[2]), "=r"(r[3]) : "r"(addr));
}

__device__ __forceinline__ void mma_bf16(float* c, const uint32_t* a,
                                         const uint32_t* b) {
    asm volatile(
        "mma.sync.aligned.m16n8k16.row.col.f32.bf16.bf16.f32 "
        "{%0,%1,%2,%3}, {%4,%5,%6,%7}, {%8,%9}, {%0,%1,%2,%3};"
        : "+f"(c[0]), "+f"(c[1]), "+f"(c[2]), "+f"(c[3])
        : "r"(a[0]), "r"(a[1]), "r"(a[2]), "r"(a[3]), "r"(b[0]), "r"(b[1]));
}

__device__ __forceinline__ void cp16(uint32_t sdst, const void* gsrc) {
    asm volatile("cp.async.cg.shared.global [%0], [%1], 16;"
                 :: "r"(sdst), "l"(gsrc) : "memory");
}
#define CP_COMMIT asm volatile("cp.async.commit_group;" ::: "memory")
#define CP_WAIT0  asm volatile("cp.async.wait_group 0;" ::: "memory")
#define CP_WAIT1  asm volatile("cp.async.wait_group 1;" ::: "memory")

// Swizzle for 256B-pitch bf16 tiles (attention)
__device__ __forceinline__ uint32_t swz(uint32_t row, uint32_t byte) {
    uint32_t c = byte >> 4;
    return row * 256 + ((((c ^ row) & 7u) | (c & 8u)) << 4) + (byte & 15u);
}
// Swizzle for 64B-pitch (k32) GEMM tiles: 4 chunks/row, conflict-free ldsm
__device__ __forceinline__ uint32_t swzg(uint32_t row, uint32_t byte) {
    uint32_t c = byte >> 4;                 // 0..3
    return row * 64 + (((c ^ ((row >> 1) & 3u)) & 3u) << 4);
}

__device__ __forceinline__ void bf16_split(float v, __nv_bfloat16& h, __nv_bfloat16& l) {
    h = __float2bfloat16_rn(v);
    l = __float2bfloat16_rn(v - __bfloat162float(h));
}
__device__ __forceinline__ void split_pack2(float a, float b, uint32_t& h, uint32_t& l) {
    __nv_bfloat16 ha, la, hb, lb;
    bf16_split(a, ha, la); bf16_split(b, hb, lb);
    __nv_bfloat162 H = __halves2bfloat162(ha, hb);
    __nv_bfloat162 L = __halves2bfloat162(la, lb);
    h = *reinterpret_cast<uint32_t*>(&H);
    l = *reinterpret_cast<uint32_t*>(&L);
}

// ---------------------------------------------------------------------------
// Prep kernels
// ---------------------------------------------------------------------------
__global__ void split_kernel(const float* __restrict__ src) {
    size_t i = (size_t)blockIdx.x * blockDim.x + threadIdx.x;  // float4 index
    float4 v = ((const float4*)src)[i];
    uint32_t h0, l0, h1, l1;
    split_pack2(v.x, v.y, h0, l0);
    split_pack2(v.z, v.w, h1, l1);
    ((uint32_t*)g_Xh)[i * 2 + 0] = h0; ((uint32_t*)g_Xh)[i * 2 + 1] = h1;
    ((uint32_t*)g_Xl)[i * 2 + 0] = l0; ((uint32_t*)g_Xl)[i * 2 + 1] = l1;
}

__global__ void wsplit_kernel(const float* __restrict__ wq,
                              const float* __restrict__ wk,
                              const float* __restrict__ wv,
                              const float* __restrict__ wo) {
    __shared__ float tile[32][33];
    const int z = blockIdx.z;
    const float* w = (z == 0) ? wq : (z == 1) ? wk : (z == 2) ? wv : wo;
    const int n0 = blockIdx.x * 32, k0 = blockIdx.y * 32;
    const int tx = threadIdx.x, ty = threadIdx.y;  // 32 x 8
#pragma unroll
    for (int i = 0; i < 4; i++)
        tile[ty + 8 * i][tx] = w[(size_t)(k0 + ty + 8 * i) * EMBED + n0 + tx];
    __syncthreads();
#pragma unroll
    for (int i = 0; i < 4; i++) {
        float v = tile[tx][ty + 8 * i];
        __nv_bfloat16 h, l;
        bf16_split(v, h, l);
        size_t off = (size_t)(n0 + ty + 8 * i) * EMBED + k0 + tx;
        g_Wh[z][off] = h;
        g_Wl[z][off] = l;
    }
}

// ---------------------------------------------------------------------------
// mma.sync GEMM, template NPASS: 1 = single bf16 (Q,K proj), 3 = hi/lo split.
// CTA 128x128, 8 warps (64x32 warp tiles), k-chunk 32, 3-stage cp.async,
// ONE __syncthreads per chunk, 64B-pitch chunk-swizzled smem, 2 CTAs/SM.
// ---------------------------------------------------------------------------
#define G_ARR  (128 * 64)        // 8KB per 128x32 bf16 array
#define G_NCH  (EMBED / 32)      // 64 chunks

template <int NPASS>
__device__ __forceinline__ void gemm_body(
    const __nv_bfloat16* __restrict__ Ah, const __nv_bfloat16* __restrict__ Al,
    const __nv_bfloat16* __restrict__ Bh, const __nv_bfloat16* __restrict__ Bl,
    const float* __restrict__ bias, float* __restrict__ outp,
    int mode, int head, __nv_bfloat16* outh, __nv_bfloat16* outl, float scale)
{
    constexpr int NARR  = (NPASS == 3) ? 4 : 2;
    constexpr int STAGE = NARR * G_ARR;
    constexpr int BOFF  = (NPASS == 3) ? 2 * G_ARR : G_ARR;

    extern __shared__ char smem[];
    const uint32_t sbase = smem_u32(smem);

    const int tid = threadIdx.x;
    const int wid = tid >> 5, lane = tid & 31;
    const int m0 = blockIdx.y * 128;
    const int n0 = blockIdx.x * 128;

    // Loader mapping: row = tid>>1, chunk pair (tid&1)*2 + {0,1}
    const int lrow = tid >> 1;
    const int lc0  = (tid & 1) * 2;
    const char* gAh = (const char*)(Ah + (size_t)(m0 + lrow) * EMBED);
    const char* gBh = (const char*)(Bh + (size_t)(n0 + lrow) * EMBED);
    const char* gAl = (const char*)(Al + (size_t)(m0 + lrow) * EMBED);
    const char* gBl = (const char*)(Bl + (size_t)(n0 + lrow) * EMBED);
    uint32_t so0 = swzg(lrow, (lc0 + 0) * 16);
    uint32_t so1 = swzg(lrow, (lc0 + 1) * 16);

    auto load_stage = [&](int stage, int c) {
        const uint32_t s = sbase + stage * STAGE;
        const size_t g0 = (size_t)c * 64 + lc0 * 16;
        cp16(s + so0,        gAh + g0);
        cp16(s + so1,        gAh + g0 + 16);
        cp16(s + BOFF + so0, gBh + g0);
        cp16(s + BOFF + so1, gBh + g0 + 16);
        if (NPASS == 3) {
            cp16(s + G_ARR + so0,     gAl + g0);
            cp16(s + G_ARR + so1,     gAl + g0 + 16);
            cp16(s + 3 * G_ARR + so0, gBl + g0);
            cp16(s + 3 * G_ARR + so1, gBl + g0 + 16);
        }
    };

    float acc[4][4][4];
#pragma unroll
    for (int i = 0; i < 4; i++)
#pragma unroll
        for (int j = 0; j < 4; j++)
#pragma unroll
            for (int r = 0; r < 4; r++) acc[i][j][r] = 0.0f;

    const int wm = (wid & 1) * 64;
    const int wn = (wid >> 1) * 32;
    const uint32_t arow = lane & 15;
    const uint32_t akh  = lane >> 4;
    const uint32_t bn   = (lane & 7) + ((lane >> 4) & 1) * 8;
    const uint32_t bkh  = (lane >> 3) & 1;

    auto compute = [&](int stage) {
        const uint32_t s = sbase + stage * STAGE;
#pragma unroll
        for (int ks = 0; ks < 2; ks++) {
            uint32_t bh[2][4], bl[2][4];
#pragma unroll
            for (int jj = 0; jj < 2; jj++) {
                const uint32_t bd = s + BOFF +
                    swzg(wn + jj * 16 + bn, ks * 32 + bkh * 16);
                ldsm4(bh[jj], bd);
                if (NPASS == 3) ldsm4(bl[jj], bd + G_ARR);
            }
#pragma unroll
            for (int mi = 0; mi < 4; mi++) {
                const uint32_t ad = s +
                    swzg(wm + mi * 16 + arow, ks * 32 + akh * 16);
                uint32_t ah[4];
                ldsm4(ah, ad);
#pragma unroll
                for (int nj = 0; nj < 4; nj++)
                    mma_bf16(acc[mi][nj], ah, &bh[nj >> 1][(nj & 1) * 2]);
                if (NPASS == 3) {
#pragma unroll
                    for (int nj = 0; nj < 4; nj++)
                        mma_bf16(acc[mi][nj], ah, &bl[nj >> 1][(nj & 1) * 2]);
                    uint32_t al[4];
                    ldsm4(al, ad + G_ARR);
#pragma unroll
                    for (int nj = 0; nj < 4; nj++)
                        mma_bf16(acc[mi][nj], al, &bh[nj >> 1][(nj & 1) * 2]);
                }
            }
        }
    };

    // 3-stage pipeline, 2 chunks in flight, ONE sync per chunk
    load_stage(0, 0); CP_COMMIT;
    load_stage(1, 1); CP_COMMIT;
    int s_ld = 2, s_cp = 0;
    for (int c = 0; c < G_NCH; c++) {
        CP_WAIT1;            // chunk c's group complete (this thread)
        __syncthreads();     // all threads complete + stage s_ld free
        if (c + 2 < G_NCH) load_stage(s_ld, c + 2);
        CP_COMMIT;
        compute(s_cp);
        if (++s_ld == 3) s_ld = 0;
        if (++s_cp == 3) s_cp = 0;
    }

    const int r0 = lane >> 2, c0 = (lane & 3) * 2;
#pragma unroll
    for (int mi = 0; mi < 4; mi++) {
#pragma unroll
        for (int ro = 0; ro < 2; ro++) {
            const int m = m0 + wm + mi * 16 + r0 + ro * 8;
            if (mode == 0) {
                float* dst = outp + (size_t)m * EMBED + n0;
#pragma unroll
                for (int nj = 0; nj < 4; nj++) {
                    const int nl = wn + nj * 8 + c0;
                    float2 v;
                    v.x = acc[mi][nj][ro * 2 + 0] + __ldg(&bias[n0 + nl]);
                    v.y = acc[mi][nj][ro * 2 + 1] + __ldg(&bias[n0 + nl + 1]);
                    *(float2*)(dst + nl) = v;
                }
            } else {
                const int b = m >> 11, t = m & 2047;
                const size_t base = ((size_t)(b * NHEAD + head) * SEQ + t) * HDIM;
#pragma unroll
                for (int nj = 0; nj < 4; nj++) {
                    const int nl = wn + nj * 8 + c0;
                    float vx = (acc[mi][nj][ro * 2 + 0] + __ldg(&bias[n0 + nl])) * scale;
                    float vy = (acc[mi][nj][ro * 2 + 1] + __ldg(&bias[n0 + nl + 1])) * scale;
                    uint32_t h, l;
                    split_pack2(vx, vy, h, l);
                    *(uint32_t*)(outh + base + nl) = h;
                    if (outl) *(uint32_t*)(outl + base + nl) = l;
                }
            }
        }
    }
}

// Q and K projections: single-pass bf16 (numerics: |S| small, softmax abs-err)
__global__ __launch_bounds__(256, 2) void qk_mma_kernel(
    const float* bq, const float* bk)
{
    const int z = blockIdx.z;   // 0 = Q, 1 = K
    gemm_body<1>(g_Xh, nullptr, g_Wh[z], nullptr,
                 z ? bk : bq, nullptr, 1, blockIdx.x,
                 z ? g_Kh : g_Qh, nullptr, z ? 1.0f : kScale);
}

// V projection: 3-pass hi/lo (output-path precision)
__global__ __launch_bounds__(256, 2) void v_mma_kernel(const float* bv)
{
    gemm_body<3>(g_Xh, g_Xl, g_Wh[2], g_Wl[2], bv, nullptr, 1, blockIdx.x,
                 g_Vh, g_Vl, 1.0f);
}

// Output projection: 3-pass hi/lo
__global__ __launch_bounds__(256, 2) void o_mma_kernel(
    const float* bo, float* out)
{
    gemm_body<3>(g_Ah, g_Al, g_Wh[3], g_Wl[3], bo, out, 0, 0,
                 nullptr, nullptr, 1.0f);
}

// ---------------------------------------------------------------------------
// FA2 attention. 128 threads (4 warps x 16 q-rows), 64 q-rows/CTA, 64-key
// tiles double-buffered. S = QK^T single bf16 (fp32 acc); PV 3-pass hi/lo.
// Q fragments resident in registers. Smem 112KB -> 2 CTAs/SM.
// ---------------------------------------------------------------------------
#define AKV_K     (64 * 256)               // 16 KB: one 64x128 bf16 tile
#define AT_STAGE  (3 * AKV_K)              // Kh, Vh, Vl = 48 KB
#define AT_Q      (64 * 256)               // 16 KB (Q single bf16)
#define AT_SMEM   (AT_Q + 2 * AT_STAGE)    // 114688 B = 112 KB
#define NKT       (SEQ / 64)               // 32

__global__ __launch_bounds__(128, 2) void attn_mma_kernel()
{
    extern __shared__ char smem[];
    const uint32_t sq  = smem_u32(smem);
    const uint32_t skv = sq + AT_Q;
    const int tid = threadIdx.x, lane = tid & 31, wid = tid >> 5;
    const int bh = blockIdx.y;
    const int q0 = blockIdx.x * 64;
    const size_t bho = (size_t)bh * SEQ * HDIM;

    const char* gK  = (const char*)(g_Kh + bho);
    const char* gVh = (const char*)(g_Vh + bho);
    const char* gVl = (const char*)(g_Vl + bho);

    auto load_stage = [&](int stage, int kt) {
        const uint32_t s = skv + stage * AT_STAGE;
        const int row = tid >> 1;
        const size_t go = (size_t)(kt * 64 + row) * 256;   // bytes
#pragma unroll
        for (int i = 0; i < 8; i++) {
            const uint32_t c = (tid & 1) * 8 + i;
            const uint32_t so = swz(row, c * 16);
            cp16(s + so,             gK  + go + c * 16);
            cp16(s + AKV_K + so,     gVh + go + c * 16);
            cp16(s + 2 * AKV_K + so, gVl + go + c * 16);
        }
    };

    // Q tile (64 rows, single bf16) + stage 0
    {
        const int row = tid >> 1;
        const char* gq = (const char*)(g_Qh + bho + (size_t)(q0 + row) * HDIM);
#pragma unroll
        for (int i = 0; i < 8; i++) {
            const uint32_t c = (tid & 1) * 8 + i;
            cp16(sq + swz(row, c * 16), gq + c * 16);
        }
        CP_COMMIT;
    }
    load_stage(0, 0); CP_COMMIT;

    // Q fragments -> registers (Q group done; stage-0 may stay in flight)
    CP_WAIT1;
    __syncthreads();
    uint32_t qf[8][4];
    {
        const uint32_t qrow = wid * 16 + (lane & 15);
        const uint32_t qkh = (lane >> 4) * 16;
#pragma unroll
        for (int ks = 0; ks < 8; ks++)
            ldsm4(qf[ks], sq + swz(qrow, ks * 32 + qkh));
    }

    float oacc[16][4];
#pragma unroll
    for (int j = 0; j < 16; j++)
#pragma unroll
        for (int r = 0; r < 4; r++) oacc[j][r] = 0.0f;
    float mrow[2] = {-1e30f, -1e30f}, lrow[2] = {0.0f, 0.0f};

    const uint32_t krow_off = (lane & 7) + ((lane >> 4) & 1) * 8;  // S-phase
    const uint32_t kb_off   = ((lane >> 3) & 1) * 16;
    const uint32_t vrow_off = (lane & 7) + ((lane >> 3) & 1) * 8;  // PV-phase
    const uint32_t vb_off   = ((lane >> 4) & 1) * 16;

    for (int kt = 0; kt < NKT; kt++) {
        if (kt + 1 < NKT) { load_stage((kt + 1) & 1, kt + 1); CP_COMMIT; CP_WAIT1; }
        else              { CP_WAIT0; }
        __syncthreads();

        const uint32_t s = skv + (kt & 1) * AT_STAGE;

        // ---- S = Q K^T, single bf16, fp32 acc ----
        float sacc[8][4];
#pragma unroll
        for (int j = 0; j < 8; j++)
#pragma unroll
            for (int r = 0; r < 4; r++) sacc[j][r] = 0.0f;

#pragma unroll
        for (int ks = 0; ks < 8; ks++) {
            uint32_t kb[4][4];
#pragma unroll
            for (int jp = 0; jp < 4; jp++)
                ldsm4(kb[jp], s + swz(jp * 16 + krow_off, ks * 32 + kb_off));
#pragma unroll
            for (int jp = 0; jp < 4; jp++) {
                mma_bf16(sacc[2*jp],   qf[ks], &kb[jp][0]);
                mma_bf16(sacc[2*jp+1], qf[ks], &kb[jp][2]);
            }
        }

        // ---- Online softmax (rows lane>>2 and lane>>2 + 8) ----
#pragma unroll
        for (int rr = 0; rr < 2; rr++) {
            float mt = -1e30f;
#pragma unroll
            for (int j = 0; j < 8; j++)
                mt = fmaxf(mt, fmaxf(sacc[j][rr*2], sacc[j][rr*2+1]));
            mt = fmaxf(mt, __shfl_xor_sync(0xffffffffu, mt, 1));
            mt = fmaxf(mt, __shfl_xor_sync(0xffffffffu, mt, 2));
            const float mn = fmaxf(mrow[rr], mt);
            const float alpha = __expf(mrow[rr] - mn);
            float ls = 0.0f;
#pragma unroll
            for (int j = 0; j < 8; j++) {
                float p0 = __expf(sacc[j][rr*2]   - mn);
                float p1 = __expf(sacc[j][rr*2+1] - mn);
                sacc[j][rr*2] = p0; sacc[j][rr*2+1] = p1;
                ls += p0 + p1;
            }
            ls += __shfl_xor_sync(0xffffffffu, ls, 1);
            ls += __shfl_xor_sync(0xffffffffu, ls, 2);
            lrow[rr] = lrow[rr] * alpha + ls;
            mrow[rr] = mn;
#pragma unroll
            for (int j = 0; j < 16; j++) {
                oacc[j][rr*2]   *= alpha;
                oacc[j][rr*2+1] *= alpha;
            }
        }

        // ---- O += P V, 3-pass hi/lo (P packed in-register) ----
#pragma unroll
        for (int ks = 0; ks < 4; ks++) {
            uint32_t pah[4], pal[4];
#pragma unroll
            for (int half = 0; half < 2; half++) {
                const float* sc = sacc[2*ks + half];
                split_pack2(sc[0], sc[1], pah[2*half],   pal[2*half]);
                split_pack2(sc[2], sc[3], pah[2*half+1], pal[2*half+1]);
            }
#pragma unroll
            for (int jp = 0; jp < 8; jp++) {
                uint32_t vbh[4], vbl[4];
                const uint32_t so = swz(ks * 16 + vrow_off, jp * 32 + vb_off);
                ldsm4t(vbh, s + AKV_K + so);
                ldsm4t(vbl, s + 2 * AKV_K + so);
                mma_bf16(oacc[2*jp],   pah, &vbh[0]);
                mma_bf16(oacc[2*jp],   pah, &vbl[0]);
                mma_bf16(oacc[2*jp],   pal, &vbh[0]);
                mma_bf16(oacc[2*jp+1], pah, &vbh[2]);
                mma_bf16(oacc[2*jp+1], pah, &vbl[2]);
                mma_bf16(oacc[2*jp+1], pal, &vbh[2]);
            }
        }
        __syncthreads();
    }

    // ---- Epilogue: normalize, split hi/lo, write [b,t,h*128+hd] ----
    const int b_ = bh >> 4, h_ = bh & 15;
    const float inv0 = 1.0f / lrow[0], inv1 = 1.0f / lrow[1];
#pragma unroll
    for (int rr = 0; rr < 2; rr++) {
        const int t = q0 + wid * 16 + (lane >> 2) + rr * 8;
        const size_t base = ((size_t)(b_ * SEQ + t)) * EMBED + h_ * HDIM;
        const float inv = rr ? inv1 : inv0;
#pragma unroll
        for (int j = 0; j < 16; j++) {
            const int hd = j * 8 + (lane & 3) * 2;
            uint32_t h, l;
            split_pack2(oacc[j][rr*2] * inv, oacc[j][rr*2+1] * inv, h, l);
            *(uint32_t*)(g_Ah + base + hd) = h;
            *(uint32_t*)(g_Al + base + hd) = l;
        }
    }
}

// ---------------------------------------------------------------------------
// Launch sequence
// ---------------------------------------------------------------------------
#define GEMM_SMEM1 (3 * 2 * G_ARR)   // 49152
#define GEMM_SMEM3 (3 * 4 * G_ARR)   // 98304

extern "C" void kernel_launch(void* const* d_in, const int* in_sizes, int n_in,
                              void* d_out, int out_size)
{
    (void)in_sizes; (void)n_in; (void)out_size;
    const float* x  = (const float*)d_in[0];
    const float* wq = (const float*)d_in[1];
    const float* bq = (const float*)d_in[2];
    const float* wk = (const float*)d_in[3];
    const float* bk = (const float*)d_in[4];
    const float* wv = (const float*)d_in[5];
    const float* bv = (const float*)d_in[6];
    const float* wo = (const float*)d_in[7];
    const float* bo = (const float*)d_in[8];
    float* out = (float*)d_out;

    cudaFuncSetAttribute(qk_mma_kernel,
                         cudaFuncAttributeMaxDynamicSharedMemorySize, GEMM_SMEM1);
    cudaFuncSetAttribute(v_mma_kernel,
                         cudaFuncAttributeMaxDynamicSharedMemorySize, GEMM_SMEM3);
    cudaFuncSetAttribute(o_mma_kernel,
                         cudaFuncAttributeMaxDynamicSharedMemorySize, GEMM_SMEM3);
    cudaFuncSetAttribute(attn_mma_kernel,
                         cudaFuncAttributeMaxDynamicSharedMemorySize, AT_SMEM);

    // 1. split x -> bf16 hi/lo
    split_kernel<<<(NTOK * EMBED / 4) / 256, 256>>>(x);
    // 2. transpose + split weights
    wsplit_kernel<<<dim3(EMBED / 32, EMBED / 32, 4), dim3(32, 8)>>>(wq, wk, wv, wo);
    // 3. Q,K projections (single-pass bf16) and V projection (3-pass)
    qk_mma_kernel<<<dim3(16, 32, 2), 256, GEMM_SMEM1>>>(bq, bk);
    v_mma_kernel<<<dim3(16, 32), 256, GEMM_SMEM3>>>(bv);
    // 4. tensor-core flash attention -> bf16 hi/lo A
    attn_mma_kernel<<<dim3(SEQ / 64, BATCH * NHEAD), 128, AT_SMEM>>>();
    // 5. output projection -> fp32 out
    o_mma_kernel<<<dim3(16, 32), 256, GEMM_SMEM3>>>(bo, out);
}

// round 16
// speedup vs baseline: 1.7333x; 1.2311x over previous
#include <cuda_runtime.h>
#include <cuda_fp16.h>
#include <cstdint>

// Problem constants
#define EMBED 2048
#define NHEAD 16
#define HDIM  128
#define BATCH 2
#define SEQ   2048
#define NTOK  (BATCH * SEQ)   // 4096

__device__ __constant__ float kScale = 0.022097086912079612f;  // 2048^-0.5

// ---------------------------------------------------------------------------
// Static device scratch (allocation-free per harness rules)
// All activations single fp16; weights fp16 hi/lo; V fp16 hi/lo.
// ---------------------------------------------------------------------------
__device__ __half g_X [(size_t)NTOK * EMBED];                    // fp16(x)
__device__ __half g_A [(size_t)NTOK * EMBED];                    // attn out fp16
__device__ __half g_Wh[4][(size_t)EMBED * EMBED];                // W^T hi: [n][k]
__device__ __half g_Wl[4][(size_t)EMBED * EMBED];                // W^T lo
__device__ __half g_Q [(size_t)BATCH * NHEAD * SEQ * HDIM];      // pre-scaled
__device__ __half g_K [(size_t)BATCH * NHEAD * SEQ * HDIM];
__device__ __half g_Vh[(size_t)BATCH * NHEAD * SEQ * HDIM];
__device__ __half g_Vl[(size_t)BATCH * NHEAD * SEQ * HDIM];

// ---------------------------------------------------------------------------
// sm_80-era PTX helpers (base-target ISA; no 'a' features — R11 constraint)
// ---------------------------------------------------------------------------
__device__ __forceinline__ uint32_t smem_u32(const void* p) {
    uint32_t a;
    asm("{ .reg .u64 t; cvta.to.shared.u64 t, %1; cvt.u32.u64 %0, t; }"
        : "=r"(a) : "l"(p));
    return a;
}

__device__ __forceinline__ void ldsm4(uint32_t* r, uint32_t addr) {
    asm volatile("ldmatrix.sync.aligned.m8n8.x4.shared.b16 {%0,%1,%2,%3}, [%4];"
                 : "=r"(r[0]), "=r"(r[1]), "=r"(r[2]), "=r"(r[3]) : "r"(addr));
}
__device__ __forceinline__ void ldsm4t(uint32_t* r, uint32_t addr) {
    asm volatile("ldmatrix.sync.aligned.m8n8.x4.trans.shared.b16 {%0,%1,%2,%3}, [%4];"
                 : "=r"(r[0]), "=r"(r[1]), "=r"(r[2]), "=r"(r[3]) : "r"(addr));
}

__device__ __forceinline__ void mma_f16(float* c, const uint32_t* a,
                                        const uint32_t* b) {
    asm volatile(
        "mma.sync.aligned.m16n8k16.row.col.f32.f16.f16.f32 "
        "{%0,%1,%2,%3}, {%4,%5,%6,%7}, {%8,%9}, {%0,%1,%2,%3};"
        : "+f"(c[0]), "+f"(c[1]), "+f"(c[2]), "+f"(c[3])
        : "r"(a[0]), "r"(a[1]), "r"(a[2]), "r"(a[3]), "r"(b[0]), "r"(b[1]));
}

__device__ __forceinline__ void cp16(uint32_t sdst, const void* gsrc) {
    asm volatile("cp.async.cg.shared.global [%0], [%1], 16;"
                 :: "r"(sdst), "l"(gsrc) : "memory");
}
#define CP_COMMIT asm volatile("cp.async.commit_group;" ::: "memory")
#define CP_WAIT0  asm volatile("cp.async.wait_group 0;" ::: "memory")
#define CP_WAIT1  asm volatile("cp.async.wait_group 1;" ::: "memory")
#define CP_WAIT2  asm volatile("cp.async.wait_group 2;" ::: "memory")

// Swizzle for 256B-pitch fp16 tiles (attention)
__device__ __forceinline__ uint32_t swz(uint32_t row, uint32_t byte) {
    uint32_t c = byte >> 4;
    return row * 256 + ((((c ^ row) & 7u) | (c & 8u)) << 4) + (byte & 15u);
}
// Swizzle for 64B-pitch (k32) GEMM tiles: 4 chunks/row, conflict-free ldsm
__device__ __forceinline__ uint32_t swzg(uint32_t row, uint32_t byte) {
    uint32_t c = byte >> 4;                 // 0..3
    return row * 64 + (((c ^ ((row >> 1) & 3u)) & 3u) << 4);
}

__device__ __forceinline__ void f16_split(float v, __half& h, __half& l) {
    h = __float2half_rn(v);
    l = __float2half_rn(v - __half2float(h));
}
__device__ __forceinline__ uint32_t pack_h2(float a, float b) {
    __half2 H = __halves2half2(__float2half_rn(a), __float2half_rn(b));
    return *reinterpret_cast<uint32_t*>(&H);
}
// split (a,b) -> packed hi half2, lo half2
__device__ __forceinline__ void split_pack2(float a, float b, uint32_t& h, uint32_t& l) {
    __half ha, la, hb, lb;
    f16_split(a, ha, la); f16_split(b, hb, lb);
    __half2 H = __halves2half2(ha, hb);
    __half2 L = __halves2half2(la, lb);
    h = *reinterpret_cast<uint32_t*>(&H);
    l = *reinterpret_cast<uint32_t*>(&L);
}

// ---------------------------------------------------------------------------
// Prep kernels
// ---------------------------------------------------------------------------
__global__ void cvt_kernel(const float* __restrict__ src) {
    size_t i = (size_t)blockIdx.x * blockDim.x + threadIdx.x;  // float4 index
    float4 v = ((const float4*)src)[i];
    ((uint32_t*)g_X)[i * 2 + 0] = pack_h2(v.x, v.y);
    ((uint32_t*)g_X)[i * 2 + 1] = pack_h2(v.z, v.w);
}

// Transpose + split: w[k][n] fp32 -> g_Wh/g_Wl[z][n][k] fp16
__global__ void wsplit_kernel(const float* __restrict__ wq,
                              const float* __restrict__ wk,
                              const float* __restrict__ wv,
                              const float* __restrict__ wo) {
    __shared__ float tile[32][33];
    const int z = blockIdx.z;
    const float* w = (z == 0) ? wq : (z == 1) ? wk : (z == 2) ? wv : wo;
    const int n0 = blockIdx.x * 32, k0 = blockIdx.y * 32;
    const int tx = threadIdx.x, ty = threadIdx.y;  // 32 x 8
#pragma unroll
    for (int i = 0; i < 4; i++)
        tile[ty + 8 * i][tx] = w[(size_t)(k0 + ty + 8 * i) * EMBED + n0 + tx];
    __syncthreads();
#pragma unroll
    for (int i = 0; i < 4; i++) {
        float v = tile[tx][ty + 8 * i];
        __half h, l;
        f16_split(v, h, l);
        size_t off = (size_t)(n0 + ty + 8 * i) * EMBED + k0 + tx;
        g_Wh[z][off] = h;
        g_Wl[z][off] = l;
    }
}

// ---------------------------------------------------------------------------
// fp16 mma.sync GEMM, NPASS: 1 = A·Wh only (Q,K proj); 2 = A·Wh + A·Wl (V,O).
// A is ALWAYS single fp16. CTA 128x128, 8 warps (64x32 warp tiles),
// k-chunk 32, 4-stage cp.async (3 in flight), one __syncthreads per chunk.
// ---------------------------------------------------------------------------
#define G_ARR  (128 * 64)        // 8KB per 128x32 fp16 array
#define G_NCH  (EMBED / 32)      // 64 chunks

template <int NPASS>
__device__ __forceinline__ void gemm_body(
    const __half* __restrict__ A,
    const __half* __restrict__ Bh, const __half* __restrict__ Bl,
    const float* __restrict__ bias, float* __restrict__ outp,
    int mode, int head, __half* outh, __half* outl, float scale)
{
    constexpr int NARR  = NPASS + 1;       // A, Bh[, Bl]
    constexpr int STAGE = NARR * G_ARR;

    extern __shared__ char smem[];
    const uint32_t sbase = smem_u32(smem);

    const int tid = threadIdx.x;
    const int wid = tid >> 5, lane = tid & 31;
    const int m0 = blockIdx.y * 128;
    const int n0 = blockIdx.x * 128;

    // Loader: row = tid>>1, chunk pair (tid&1)*2 + {0,1}
    const int lrow = tid >> 1;
    const int lc0  = (tid & 1) * 2;
    const char* gA  = (const char*)(A  + (size_t)(m0 + lrow) * EMBED);
    const char* gBh = (const char*)(Bh + (size_t)(n0 + lrow) * EMBED);
    const char* gBl = (NPASS == 2) ? (const char*)(Bl + (size_t)(n0 + lrow) * EMBED)
                                   : nullptr;
    const uint32_t so0 = swzg(lrow, (lc0 + 0) * 16);
    const uint32_t so1 = swzg(lrow, (lc0 + 1) * 16);

    auto load_stage = [&](int stage, int c) {
        const uint32_t s = sbase + stage * STAGE;
        const size_t g0 = (size_t)c * 64 + lc0 * 16;
        cp16(s + so0,         gA + g0);
        cp16(s + so1,         gA + g0 + 16);
        cp16(s + G_ARR + so0, gBh + g0);
        cp16(s + G_ARR + so1, gBh + g0 + 16);
        if (NPASS == 2) {
            cp16(s + 2 * G_ARR + so0, gBl + g0);
            cp16(s + 2 * G_ARR + so1, gBl + g0 + 16);
        }
    };

    float acc[4][4][4];
#pragma unroll
    for (int i = 0; i < 4; i++)
#pragma unroll
        for (int j = 0; j < 4; j++)
#pragma unroll
            for (int r = 0; r < 4; r++) acc[i][j][r] = 0.0f;

    const int wm = (wid & 1) * 64;
    const int wn = (wid >> 1) * 32;
    const uint32_t arow = lane & 15;
    const uint32_t akh  = lane >> 4;
    const uint32_t bn   = (lane & 7) + ((lane >> 4) & 1) * 8;
    const uint32_t bkh  = (lane >> 3) & 1;

    auto compute = [&](int stage) {
        const uint32_t s = sbase + stage * STAGE;
#pragma unroll
        for (int ks = 0; ks < 2; ks++) {
            uint32_t bh[2][4], bl[2][4];
#pragma unroll
            for (int jj = 0; jj < 2; jj++) {
                const uint32_t bd = s + G_ARR +
                    swzg(wn + jj * 16 + bn, ks * 32 + bkh * 16);
                ldsm4(bh[jj], bd);
                if (NPASS == 2) ldsm4(bl[jj], bd + G_ARR);
            }
#pragma unroll
            for (int mi = 0; mi < 4; mi++) {
                uint32_t af[4];
                ldsm4(af, s + swzg(wm + mi * 16 + arow, ks * 32 + akh * 16));
#pragma unroll
                for (int nj = 0; nj < 4; nj++)
                    mma_f16(acc[mi][nj], af, &bh[nj >> 1][(nj & 1) * 2]);
                if (NPASS == 2) {
#pragma unroll
                    for (int nj = 0; nj < 4; nj++)
                        mma_f16(acc[mi][nj], af, &bl[nj >> 1][(nj & 1) * 2]);
                }
            }
        }
    };

    // 4-stage pipeline, 3 in flight, one sync per chunk
    load_stage(0, 0); CP_COMMIT;
    load_stage(1, 1); CP_COMMIT;
    load_stage(2, 2); CP_COMMIT;
    for (int c = 0; c < G_NCH; c++) {
        CP_WAIT2;            // chunk c's group complete (this thread)
        __syncthreads();     // all threads complete; stage (c+3)&3 free
        if (c + 3 < G_NCH) load_stage((c + 3) & 3, c + 3);
        CP_COMMIT;
        compute(c & 3);
    }

    const int r0 = lane >> 2, c0 = (lane & 3) * 2;
#pragma unroll
    for (int mi = 0; mi < 4; mi++) {
#pragma unroll
        for (int ro = 0; ro < 2; ro++) {
            const int m = m0 + wm + mi * 16 + r0 + ro * 8;
            if (mode == 0) {
                float* dst = outp + (size_t)m * EMBED + n0;
#pragma unroll
                for (int nj = 0; nj < 4; nj++) {
                    const int nl = wn + nj * 8 + c0;
                    float2 v;
                    v.x = acc[mi][nj][ro * 2 + 0] + __ldg(&bias[n0 + nl]);
                    v.y = acc[mi][nj][ro * 2 + 1] + __ldg(&bias[n0 + nl + 1]);
                    *(float2*)(dst + nl) = v;
                }
            } else {
                const int b = m >> 11, t = m & 2047;
                const size_t base = ((size_t)(b * NHEAD + head) * SEQ + t) * HDIM;
#pragma unroll
                for (int nj = 0; nj < 4; nj++) {
                    const int nl = wn + nj * 8 + c0;
                    float vx = (acc[mi][nj][ro * 2 + 0] + __ldg(&bias[n0 + nl])) * scale;
                    float vy = (acc[mi][nj][ro * 2 + 1] + __ldg(&bias[n0 + nl + 1])) * scale;
                    if (outl) {
                        uint32_t h, l;
                        split_pack2(vx, vy, h, l);
                        *(uint32_t*)(outh + base + nl) = h;
                        *(uint32_t*)(outl + base + nl) = l;
                    } else {
                        *(uint32_t*)(outh + base + nl) = pack_h2(vx, vy);
                    }
                }
            }
        }
    }
}

// Q and K projections: 1-pass fp16
__global__ __launch_bounds__(256, 2) void qk_mma_kernel(
    const float* bq, const float* bk)
{
    const int z = blockIdx.z;   // 0 = Q, 1 = K
    gemm_body<1>(g_X, g_Wh[z], nullptr,
                 z ? bk : bq, nullptr, 1, blockIdx.x,
                 z ? g_K : g_Q, nullptr, z ? 1.0f : kScale);
}

// V projection: 2-pass (X·Wh + X·Wl), result split hi/lo for PV
__global__ __launch_bounds__(256, 2) void v_mma_kernel(const float* bv)
{
    gemm_body<2>(g_X, g_Wh[2], g_Wl[2], bv, nullptr, 1, blockIdx.x,
                 g_Vh, g_Vl, 1.0f);
}

// Output projection: 2-pass (A·Wh + A·Wl), fp32 out
__global__ __launch_bounds__(256, 2) void o_mma_kernel(
    const float* bo, float* out)
{
    gemm_body<2>(g_A, g_Wh[3], g_Wl[3], bo, out, 0, 0,
                 nullptr, nullptr, 1.0f);
}

// ---------------------------------------------------------------------------
// FA2 attention, fp16. 128 threads (4 warps x 16 q-rows), 64 q-rows/CTA,
// 64-key tiles double-buffered. S = QK^T 1-pass; PV = P·Vh + P·Vl (2-pass,
// P unsplit). Q fragments in registers. Smem 112KB -> 2 CTAs/SM.
// ---------------------------------------------------------------------------
#define AKV_K     (64 * 256)               // 16 KB: one 64x128 fp16 tile
#define AT_STAGE  (3 * AKV_K)              // K, Vh, Vl = 48 KB
#define AT_Q      (64 * 256)               // 16 KB
#define AT_SMEM   (AT_Q + 2 * AT_STAGE)    // 114688 B = 112 KB
#define NKT       (SEQ / 64)               // 32

__global__ __launch_bounds__(128, 2) void attn_mma_kernel()
{
    extern __shared__ char smem[];
    const uint32_t sq  = smem_u32(smem);
    const uint32_t skv = sq + AT_Q;
    const int tid = threadIdx.x, lane = tid & 31, wid = tid >> 5;
    const int bh = blockIdx.y;
    const int q0 = blockIdx.x * 64;
    const size_t bho = (size_t)bh * SEQ * HDIM;

    const char* gK  = (const char*)(g_K  + bho);
    const char* gVh = (const char*)(g_Vh + bho);
    const char* gVl = (const char*)(g_Vl + bho);

    auto load_stage = [&](int stage, int kt) {
        const uint32_t s = skv + stage * AT_STAGE;
        const int row = tid >> 1;
        const size_t go = (size_t)(kt * 64 + row) * 256;   // bytes
#pragma unroll
        for (int i = 0; i < 8; i++) {
            const uint32_t c = (tid & 1) * 8 + i;
            const uint32_t so = swz(row, c * 16);
            cp16(s + so,             gK  + go + c * 16);
            cp16(s + AKV_K + so,     gVh + go + c * 16);
            cp16(s + 2 * AKV_K + so, gVl + go + c * 16);
        }
    };

    // Q tile + stage 0
    {
        const int row = tid >> 1;
        const char* gq = (const char*)(g_Q + bho + (size_t)(q0 + row) * HDIM);
#pragma unroll
        for (int i = 0; i < 8; i++) {
            const uint32_t c = (tid & 1) * 8 + i;
            cp16(sq + swz(row, c * 16), gq + c * 16);
        }
        CP_COMMIT;
    }
    load_stage(0, 0); CP_COMMIT;

    // Q fragments -> registers (stage 0 may remain in flight)
    CP_WAIT1;
    __syncthreads();
    uint32_t qf[8][4];
    {
        const uint32_t qrow = wid * 16 + (lane & 15);
        const uint32_t qkh = (lane >> 4) * 16;
#pragma unroll
        for (int ks = 0; ks < 8; ks++)
            ldsm4(qf[ks], sq + swz(qrow, ks * 32 + qkh));
    }

    float oacc[16][4];
#pragma unroll
    for (int j = 0; j < 16; j++)
#pragma unroll
        for (int r = 0; r < 4; r++) oacc[j][r] = 0.0f;
    float mrow[2] = {-1e30f, -1e30f}, lrow[2] = {0.0f, 0.0f};

    const uint32_t krow_off = (lane & 7) + ((lane >> 4) & 1) * 8;  // S-phase
    const uint32_t kb_off   = ((lane >> 3) & 1) * 16;
    const uint32_t vrow_off = (lane & 7) + ((lane >> 3) & 1) * 8;  // PV-phase
    const uint32_t vb_off   = ((lane >> 4) & 1) * 16;

    for (int kt = 0; kt < NKT; kt++) {
        if (kt + 1 < NKT) { load_stage((kt + 1) & 1, kt + 1); CP_COMMIT; CP_WAIT1; }
        else              { CP_WAIT0; }
        __syncthreads();

        const uint32_t s = skv + (kt & 1) * AT_STAGE;

        // ---- S = Q K^T, 1-pass fp16, fp32 acc ----
        float sacc[8][4];
#pragma unroll
        for (int j = 0; j < 8; j++)
#pragma unroll
            for (int r = 0; r < 4; r++) sacc[j][r] = 0.0f;

#pragma unroll
        for (int ks = 0; ks < 8; ks++) {
            uint32_t kb[4][4];
#pragma unroll
            for (int jp = 0; jp < 4; jp++)
                ldsm4(kb[jp], s + swz(jp * 16 + krow_off, ks * 32 + kb_off));
#pragma unroll
            for (int jp = 0; jp < 4; jp++) {
                mma_f16(sacc[2*jp],   qf[ks], &kb[jp][0]);
                mma_f16(sacc[2*jp+1], qf[ks], &kb[jp][2]);
            }
        }

        // ---- Online softmax (rows lane>>2 and lane>>2 + 8) ----
#pragma unroll
        for (int rr = 0; rr < 2; rr++) {
            float mt = -1e30f;
#pragma unroll
            for (int j = 0; j < 8; j++)
                mt = fmaxf(mt, fmaxf(sacc[j][rr*2], sacc[j][rr*2+1]));
            mt = fmaxf(mt, __shfl_xor_sync(0xffffffffu, mt, 1));
            mt = fmaxf(mt, __shfl_xor_sync(0xffffffffu, mt, 2));
            const float mn = fmaxf(mrow[rr], mt);
            const float alpha = __expf(mrow[rr] - mn);
            float ls = 0.0f;
#pragma unroll
            for (int j = 0; j < 8; j++) {
                float p0 = __expf(sacc[j][rr*2]   - mn);
                float p1 = __expf(sacc[j][rr*2+1] - mn);
                sacc[j][rr*2] = p0; sacc[j][rr*2+1] = p1;
                ls += p0 + p1;
            }
            ls += __shfl_xor_sync(0xffffffffu, ls, 1);
            ls += __shfl_xor_sync(0xffffffffu, ls, 2);
            lrow[rr] = lrow[rr] * alpha + ls;
            mrow[rr] = mn;
#pragma unroll
            for (int j = 0; j < 16; j++) {
                oacc[j][rr*2]   *= alpha;
                oacc[j][rr*2+1] *= alpha;
            }
        }

        // ---- O += P·Vh + P·Vl (P unsplit fp16) ----
#pragma unroll
        for (int ks = 0; ks < 4; ks++) {
            uint32_t pa[4];
#pragma unroll
            for (int half = 0; half < 2; half++) {
                const float* sc = sacc[2*ks + half];
                pa[2*half]   = pack_h2(sc[0], sc[1]);
                pa[2*half+1] = pack_h2(sc[2], sc[3]);
            }
#pragma unroll
            for (int jp = 0; jp < 8; jp++) {
                uint32_t vbh[4], vbl[4];
                const uint32_t so = swz(ks * 16 + vrow_off, jp * 32 + vb_off);
                ldsm4t(vbh, s + AKV_K + so);
                ldsm4t(vbl, s + 2 * AKV_K + so);
                mma_f16(oacc[2*jp],   pa, &vbh[0]);
                mma_f16(oacc[2*jp],   pa, &vbl[0]);
                mma_f16(oacc[2*jp+1], pa, &vbh[2]);
                mma_f16(oacc[2*jp+1], pa, &vbl[2]);
            }
        }
        __syncthreads();
    }

    // ---- Epilogue: normalize, write single fp16 [b,t,h*128+hd] ----
    const int b_ = bh >> 4, h_ = bh & 15;
    const float inv0 = 1.0f / lrow[0], inv1 = 1.0f / lrow[1];
#pragma unroll
    for (int rr = 0; rr < 2; rr++) {
        const int t = q0 + wid * 16 + (lane >> 2) + rr * 8;
        const size_t base = ((size_t)(b_ * SEQ + t)) * EMBED + h_ * HDIM;
        const float inv = rr ? inv1 : inv0;
#pragma unroll
        for (int j = 0; j < 16; j++) {
            const int hd = j * 8 + (lane & 3) * 2;
            *(uint32_t*)(g_A + base + hd) =
                pack_h2(oacc[j][rr*2] * inv, oacc[j][rr*2+1] * inv);
        }
    }
}

// ---------------------------------------------------------------------------
// Launch sequence
// ---------------------------------------------------------------------------
#define GEMM_SMEM1 (4 * 2 * G_ARR)   // 65536
#define GEMM_SMEM2 (4 * 3 * G_ARR)   // 98304

extern "C" void kernel_launch(void* const* d_in, const int* in_sizes, int n_in,
                              void* d_out, int out_size)
{
    (void)in_sizes; (void)n_in; (void)out_size;
    const float* x  = (const float*)d_in[0];
    const float* wq = (const float*)d_in[1];
    const float* bq = (const float*)d_in[2];
    const float* wk = (const float*)d_in[3];
    const float* bk = (const float*)d_in[4];
    const float* wv = (const float*)d_in[5];
    const float* bv = (const float*)d_in[6];
    const float* wo = (const float*)d_in[7];
    const float* bo = (const float*)d_in[8];
    float* out = (float*)d_out;

    cudaFuncSetAttribute(qk_mma_kernel,
                         cudaFuncAttributeMaxDynamicSharedMemorySize, GEMM_SMEM1);
    cudaFuncSetAttribute(v_mma_kernel,
                         cudaFuncAttributeMaxDynamicSharedMemorySize, GEMM_SMEM2);
    cudaFuncSetAttribute(o_mma_kernel,
                         cudaFuncAttributeMaxDynamicSharedMemorySize, GEMM_SMEM2);
    cudaFuncSetAttribute(attn_mma_kernel,
                         cudaFuncAttributeMaxDynamicSharedMemorySize, AT_SMEM);

    // 1. convert x -> fp16
    cvt_kernel<<<(NTOK * EMBED / 4) / 256, 256>>>(x);
    // 2. transpose + split weights (fp16 hi/lo)
    wsplit_kernel<<<dim3(EMBED / 32, EMBED / 32, 4), dim3(32, 8)>>>(wq, wk, wv, wo);
    // 3. Q,K projections (1-pass) and V projection (2-pass)
    qk_mma_kernel<<<dim3(16, 32, 2), 256, GEMM_SMEM1>>>(bq, bk);
    v_mma_kernel<<<dim3(16, 32), 256, GEMM_SMEM2>>>(bv);
    // 4. tensor-core flash attention -> fp16 A
    attn_mma_kernel<<<dim3(SEQ / 64, BATCH * NHEAD), 128, AT_SMEM>>>();
    // 5. output projection (2-pass) -> fp32 out
    o_mma_kernel<<<dim3(16, 32), 256, GEMM_SMEM2>>>(bo, out);
}

// round 17
// speedup vs baseline: 2.2375x; 1.2909x over previous
#include <cuda_runtime.h>
#include <cuda_fp16.h>
#include <cstdint>

// Problem constants
#define EMBED 2048
#define NHEAD 16
#define HDIM  128
#define BATCH 2
#define SEQ   2048
#define NTOK  (BATCH * SEQ)   // 4096

__device__ __constant__ float kScale = 0.022097086912079612f;  // 2048^-0.5

// ---------------------------------------------------------------------------
// Static device scratch (allocation-free per harness rules)
// ---------------------------------------------------------------------------
__device__ __half g_X [(size_t)NTOK * EMBED];                    // fp16(x)
__device__ __half g_A [(size_t)NTOK * EMBED];                    // attn out fp16
__device__ __half g_Wh[4][(size_t)EMBED * EMBED];                // W^T hi: [n][k]
__device__ __half g_Wl[4][(size_t)EMBED * EMBED];                // W^T lo
__device__ __half g_Q [(size_t)BATCH * NHEAD * SEQ * HDIM];      // pre-scaled
__device__ __half g_K [(size_t)BATCH * NHEAD * SEQ * HDIM];
__device__ __half g_V [(size_t)BATCH * NHEAD * SEQ * HDIM];

// ---------------------------------------------------------------------------
// sm_80-era PTX helpers (base-target ISA; no 'a' features — R11 constraint)
// ---------------------------------------------------------------------------
__device__ __forceinline__ uint32_t smem_u32(const void* p) {
    uint32_t a;
    asm("{ .reg .u64 t; cvta.to.shared.u64 t, %1; cvt.u32.u64 %0, t; }"
        : "=r"(a) : "l"(p));
    return a;
}

__device__ __forceinline__ void ldsm4(uint32_t* r, uint32_t addr) {
    asm volatile("ldmatrix.sync.aligned.m8n8.x4.shared.b16 {%0,%1,%2,%3}, [%4];"
                 : "=r"(r[0]), "=r"(r[1]), "=r"(r[2]), "=r"(r[3]) : "r"(addr));
}
__device__ __forceinline__ void ldsm4t(uint32_t* r, uint32_t addr) {
    asm volatile("ldmatrix.sync.aligned.m8n8.x4.trans.shared.b16 {%0,%1,%2,%3}, [%4];"
                 : "=r"(r[0]), "=r"(r[1]), "=r"(r[2]), "=r"(r[3]) : "r"(addr));
}

__device__ __forceinline__ void mma_f16(float* c, const uint32_t* a,
                                        const uint32_t* b) {
    asm volatile(
        "mma.sync.aligned.m16n8k16.row.col.f32.f16.f16.f32 "
        "{%0,%1,%2,%3}, {%4,%5,%6,%7}, {%8,%9}, {%0,%1,%2,%3};"
        : "+f"(c[0]), "+f"(c[1]), "+f"(c[2]), "+f"(c[3])
        : "r"(a[0]), "r"(a[1]), "r"(a[2]), "r"(a[3]), "r"(b[0]), "r"(b[1]));
}

__device__ __forceinline__ void cp16(uint32_t sdst, const void* gsrc) {
    asm volatile("cp.async.cg.shared.global [%0], [%1], 16;"
                 :: "r"(sdst), "l"(gsrc) : "memory");
}
#define CP_COMMIT asm volatile("cp.async.commit_group;" ::: "memory")
#define CP_WAIT0  asm volatile("cp.async.wait_group 0;" ::: "memory")
#define CP_WAIT1  asm volatile("cp.async.wait_group 1;" ::: "memory")
#define CP_WAIT2  asm volatile("cp.async.wait_group 2;" ::: "memory")

// Swizzle for 256B-pitch fp16 tiles (attention)
__device__ __forceinline__ uint32_t swz(uint32_t row, uint32_t byte) {
    uint32_t c = byte >> 4;
    return row * 256 + ((((c ^ row) & 7u) | (c & 8u)) << 4) + (byte & 15u);
}
// Swizzle for 64B-pitch (k32) GEMM tiles
__device__ __forceinline__ uint32_t swzg(uint32_t row, uint32_t byte) {
    uint32_t c = byte >> 4;                 // 0..3
    return row * 64 + (((c ^ ((row >> 1) & 3u)) & 3u) << 4);
}

__device__ __forceinline__ void f16_split(float v, __half& h, __half& l) {
    h = __float2half_rn(v);
    l = __float2half_rn(v - __half2float(h));
}
__device__ __forceinline__ uint32_t pack_h2(float a, float b) {
    __half2 H = __halves2half2(__float2half_rn(a), __float2half_rn(b));
    return *reinterpret_cast<uint32_t*>(&H);
}

// ---------------------------------------------------------------------------
// Prep kernels
// ---------------------------------------------------------------------------
__global__ void cvt_kernel(const float* __restrict__ src) {
    size_t i = (size_t)blockIdx.x * blockDim.x + threadIdx.x;  // float4 index
    float4 v = ((const float4*)src)[i];
    ((uint32_t*)g_X)[i * 2 + 0] = pack_h2(v.x, v.y);
    ((uint32_t*)g_X)[i * 2 + 1] = pack_h2(v.z, v.w);
}

// Transpose + split: w[k][n] fp32 -> g_Wh/g_Wl[z][n][k] fp16
__global__ void wsplit_kernel(const float* __restrict__ wq,
                              const float* __restrict__ wk,
                              const float* __restrict__ wv,
                              const float* __restrict__ wo) {
    __shared__ float tile[32][33];
    const int z = blockIdx.z;
    const float* w = (z == 0) ? wq : (z == 1) ? wk : (z == 2) ? wv : wo;
    const int n0 = blockIdx.x * 32, k0 = blockIdx.y * 32;
    const int tx = threadIdx.x, ty = threadIdx.y;  // 32 x 8
#pragma unroll
    for (int i = 0; i < 4; i++)
        tile[ty + 8 * i][tx] = w[(size_t)(k0 + ty + 8 * i) * EMBED + n0 + tx];
    __syncthreads();
#pragma unroll
    for (int i = 0; i < 4; i++) {
        float v = tile[tx][ty + 8 * i];
        __half h, l;
        f16_split(v, h, l);
        size_t off = (size_t)(n0 + ty + 8 * i) * EMBED + k0 + tx;
        g_Wh[z][off] = h;
        g_Wl[z][off] = l;
    }
}

// ---------------------------------------------------------------------------
// fp16 mma.sync GEMM, NPASS: 1 = A·Wh (Q,K,V proj); 2 = A·Wh + A·Wl (O proj).
// CTA 128x128, 8 warps (64x32 warp tiles), k-chunk 32, 4-stage cp.async,
// one __syncthreads per chunk, A-fragment double buffering in compute.
// ---------------------------------------------------------------------------
#define G_ARR  (128 * 64)        // 8KB per 128x32 fp16 array
#define G_NCH  (EMBED / 32)      // 64 chunks

template <int NPASS>
__device__ __forceinline__ void gemm_body(
    const __half* __restrict__ A,
    const __half* __restrict__ Bh, const __half* __restrict__ Bl,
    const float* __restrict__ bias, float* __restrict__ outp,
    int mode, int head, __half* outh, float scale)
{
    constexpr int NARR  = NPASS + 1;       // A, Bh[, Bl]
    constexpr int STAGE = NARR * G_ARR;

    extern __shared__ char smem[];
    const uint32_t sbase = smem_u32(smem);

    const int tid = threadIdx.x;
    const int wid = tid >> 5, lane = tid & 31;
    const int m0 = blockIdx.y * 128;
    const int n0 = blockIdx.x * 128;

    const int lrow = tid >> 1;
    const int lc0  = (tid & 1) * 2;
    const char* gA  = (const char*)(A  + (size_t)(m0 + lrow) * EMBED);
    const char* gBh = (const char*)(Bh + (size_t)(n0 + lrow) * EMBED);
    const char* gBl = (NPASS == 2) ? (const char*)(Bl + (size_t)(n0 + lrow) * EMBED)
                                   : nullptr;
    const uint32_t so0 = swzg(lrow, (lc0 + 0) * 16);
    const uint32_t so1 = swzg(lrow, (lc0 + 1) * 16);

    auto load_stage = [&](int stage, int c) {
        const uint32_t s = sbase + stage * STAGE;
        const size_t g0 = (size_t)c * 64 + lc0 * 16;
        cp16(s + so0,         gA + g0);
        cp16(s + so1,         gA + g0 + 16);
        cp16(s + G_ARR + so0, gBh + g0);
        cp16(s + G_ARR + so1, gBh + g0 + 16);
        if (NPASS == 2) {
            cp16(s + 2 * G_ARR + so0, gBl + g0);
            cp16(s + 2 * G_ARR + so1, gBl + g0 + 16);
        }
    };

    float acc[4][4][4];
#pragma unroll
    for (int i = 0; i < 4; i++)
#pragma unroll
        for (int j = 0; j < 4; j++)
#pragma unroll
            for (int r = 0; r < 4; r++) acc[i][j][r] = 0.0f;

    const int wm = (wid & 1) * 64;
    const int wn = (wid >> 1) * 32;
    const uint32_t arow = lane & 15;
    const uint32_t akh  = lane >> 4;
    const uint32_t bn   = (lane & 7) + ((lane >> 4) & 1) * 8;
    const uint32_t bkh  = (lane >> 3) & 1;

    auto compute = [&](int stage) {
        const uint32_t s = sbase + stage * STAGE;
#pragma unroll
        for (int ks = 0; ks < 2; ks++) {
            uint32_t bh[2][4], bl[2][4];
#pragma unroll
            for (int jj = 0; jj < 2; jj++) {
                const uint32_t bd = s + G_ARR +
                    swzg(wn + jj * 16 + bn, ks * 32 + bkh * 16);
                ldsm4(bh[jj], bd);
                if (NPASS == 2) ldsm4(bl[jj], bd + G_ARR);
            }
            // A double-buffered: prefetch mi+1 while issuing mi's MMAs
            uint32_t afa[4], afb[4];
            ldsm4(afa, s + swzg(wm + arow, ks * 32 + akh * 16));
#pragma unroll
            for (int mi = 0; mi < 4; mi++) {
                const uint32_t* cur = (mi & 1) ? afb : afa;
                if (mi < 3)
                    ldsm4((mi & 1) ? afa : afb,
                          s + swzg(wm + (mi + 1) * 16 + arow, ks * 32 + akh * 16));
#pragma unroll
                for (int nj = 0; nj < 4; nj++)
                    mma_f16(acc[mi][nj], cur, &bh[nj >> 1][(nj & 1) * 2]);
                if (NPASS == 2) {
#pragma unroll
                    for (int nj = 0; nj < 4; nj++)
                        mma_f16(acc[mi][nj], cur, &bl[nj >> 1][(nj & 1) * 2]);
                }
            }
        }
    };

    // 4-stage pipeline, 3 in flight, one sync per chunk
    load_stage(0, 0); CP_COMMIT;
    load_stage(1, 1); CP_COMMIT;
    load_stage(2, 2); CP_COMMIT;
    for (int c = 0; c < G_NCH; c++) {
        CP_WAIT2;
        __syncthreads();
        if (c + 3 < G_NCH) load_stage((c + 3) & 3, c + 3);
        CP_COMMIT;
        compute(c & 3);
    }

    const int r0 = lane >> 2, c0 = (lane & 3) * 2;
#pragma unroll
    for (int mi = 0; mi < 4; mi++) {
#pragma unroll
        for (int ro = 0; ro < 2; ro++) {
            const int m = m0 + wm + mi * 16 + r0 + ro * 8;
            if (mode == 0) {
                float* dst = outp + (size_t)m * EMBED + n0;
#pragma unroll
                for (int nj = 0; nj < 4; nj++) {
                    const int nl = wn + nj * 8 + c0;
                    float2 v;
                    v.x = acc[mi][nj][ro * 2 + 0] + __ldg(&bias[n0 + nl]);
                    v.y = acc[mi][nj][ro * 2 + 1] + __ldg(&bias[n0 + nl + 1]);
                    *(float2*)(dst + nl) = v;
                }
            } else {
                const int b = m >> 11, t = m & 2047;
                const size_t base = ((size_t)(b * NHEAD + head) * SEQ + t) * HDIM;
#pragma unroll
                for (int nj = 0; nj < 4; nj++) {
                    const int nl = wn + nj * 8 + c0;
                    float vx = (acc[mi][nj][ro * 2 + 0] + __ldg(&bias[n0 + nl])) * scale;
                    float vy = (acc[mi][nj][ro * 2 + 1] + __ldg(&bias[n0 + nl + 1])) * scale;
                    *(uint32_t*)(outh + base + nl) = pack_h2(vx, vy);
                }
            }
        }
    }
}

// Q, K, V projections: fused, 1-pass fp16
__global__ __launch_bounds__(256, 2) void qkv_mma_kernel(
    const float* bq, const float* bk, const float* bv)
{
    const int z = blockIdx.z;   // 0 = Q, 1 = K, 2 = V
    const float* bias = (z == 0) ? bq : (z == 1) ? bk : bv;
    __half* oh = (z == 0) ? g_Q : (z == 1) ? g_K : g_V;
    gemm_body<1>(g_X, g_Wh[z], nullptr, bias, nullptr, 1, blockIdx.x,
                 oh, (z == 0) ? kScale : 1.0f);
}

// Output projection: 2-pass (A·Wh + A·Wl), fp32 out
__global__ __launch_bounds__(256, 2) void o_mma_kernel(
    const float* bo, float* out)
{
    gemm_body<2>(g_A, g_Wh[3], g_Wl[3], bo, out, 0, 0, nullptr, 1.0f);
}

// ---------------------------------------------------------------------------
// FA2 attention, fp16, all single-pass. 128 threads (4 warps x 16 q-rows),
// 64 q-rows/CTA, 64-key tiles double-buffered. Fragment double-buffering in
// both S and PV phases. Smem: Q 16KB + 2 x 32KB = 80KB -> 2 CTAs/SM.
// ---------------------------------------------------------------------------
#define AKV_K     (64 * 256)               // 16 KB: one 64x128 fp16 tile
#define AT_STAGE  (2 * AKV_K)              // K, V = 32 KB
#define AT_Q      (64 * 256)               // 16 KB
#define AT_SMEM   (AT_Q + 2 * AT_STAGE)    // 81920 B
#define NKT       (SEQ / 64)               // 32

__global__ __launch_bounds__(128, 2) void attn_mma_kernel()
{
    extern __shared__ char smem[];
    const uint32_t sq  = smem_u32(smem);
    const uint32_t skv = sq + AT_Q;
    const int tid = threadIdx.x, lane = tid & 31, wid = tid >> 5;
    const int bh = blockIdx.y;
    const int q0 = blockIdx.x * 64;
    const size_t bho = (size_t)bh * SEQ * HDIM;

    const char* gK = (const char*)(g_K + bho);
    const char* gV = (const char*)(g_V + bho);

    auto load_stage = [&](int stage, int kt) {
        const uint32_t s = skv + stage * AT_STAGE;
        const int row = tid >> 1;
        const size_t go = (size_t)(kt * 64 + row) * 256;   // bytes
#pragma unroll
        for (int i = 0; i < 8; i++) {
            const uint32_t c = (tid & 1) * 8 + i;
            const uint32_t so = swz(row, c * 16);
            cp16(s + so,         gK + go + c * 16);
            cp16(s + AKV_K + so, gV + go + c * 16);
        }
    };

    // Q tile + stage 0
    {
        const int row = tid >> 1;
        const char* gq = (const char*)(g_Q + bho + (size_t)(q0 + row) * HDIM);
#pragma unroll
        for (int i = 0; i < 8; i++) {
            const uint32_t c = (tid & 1) * 8 + i;
            cp16(sq + swz(row, c * 16), gq + c * 16);
        }
        CP_COMMIT;
    }
    load_stage(0, 0); CP_COMMIT;

    // Q fragments -> registers (stage 0 may remain in flight)
    CP_WAIT1;
    __syncthreads();
    uint32_t qf[8][4];
    {
        const uint32_t qrow = wid * 16 + (lane & 15);
        const uint32_t qkh = (lane >> 4) * 16;
#pragma unroll
        for (int ks = 0; ks < 8; ks++)
            ldsm4(qf[ks], sq + swz(qrow, ks * 32 + qkh));
    }

    float oacc[16][4];
#pragma unroll
    for (int j = 0; j < 16; j++)
#pragma unroll
        for (int r = 0; r < 4; r++) oacc[j][r] = 0.0f;
    float mrow[2] = {-1e30f, -1e30f}, lrow[2] = {0.0f, 0.0f};

    const uint32_t krow_off = (lane & 7) + ((lane >> 4) & 1) * 8;  // S-phase
    const uint32_t kb_off   = ((lane >> 3) & 1) * 16;
    const uint32_t vrow_off = (lane & 7) + ((lane >> 3) & 1) * 8;  // PV-phase
    const uint32_t vb_off   = ((lane >> 4) & 1) * 16;

    for (int kt = 0; kt < NKT; kt++) {
        if (kt + 1 < NKT) { load_stage((kt + 1) & 1, kt + 1); CP_COMMIT; CP_WAIT1; }
        else              { CP_WAIT0; }
        __syncthreads();

        const uint32_t s = skv + (kt & 1) * AT_STAGE;

        // ---- S = Q K^T, 1-pass fp16, fp32 acc; K frags double-buffered ----
        float sacc[8][4];
#pragma unroll
        for (int j = 0; j < 8; j++)
#pragma unroll
            for (int r = 0; r < 4; r++) sacc[j][r] = 0.0f;

#pragma unroll
        for (int ks = 0; ks < 8; ks++) {
            uint32_t kba[4], kbb[4];
            ldsm4(kba, s + swz(krow_off, ks * 32 + kb_off));
#pragma unroll
            for (int jp = 0; jp < 4; jp++) {
                const uint32_t* cur = (jp & 1) ? kbb : kba;
                if (jp < 3)
                    ldsm4((jp & 1) ? kba : kbb,
                          s + swz((jp + 1) * 16 + krow_off, ks * 32 + kb_off));
                mma_f16(sacc[2*jp],   qf[ks], &cur[0]);
                mma_f16(sacc[2*jp+1], qf[ks], &cur[2]);
            }
        }

        // ---- Online softmax (rows lane>>2 and lane>>2 + 8) ----
#pragma unroll
        for (int rr = 0; rr < 2; rr++) {
            float mt = -1e30f;
#pragma unroll
            for (int j = 0; j < 8; j++)
                mt = fmaxf(mt, fmaxf(sacc[j][rr*2], sacc[j][rr*2+1]));
            mt = fmaxf(mt, __shfl_xor_sync(0xffffffffu, mt, 1));
            mt = fmaxf(mt, __shfl_xor_sync(0xffffffffu, mt, 2));
            const float mn = fmaxf(mrow[rr], mt);
            const float alpha = __expf(mrow[rr] - mn);
            float ls = 0.0f;
#pragma unroll
            for (int j = 0; j < 8; j++) {
                float p0 = __expf(sacc[j][rr*2]   - mn);
                float p1 = __expf(sacc[j][rr*2+1] - mn);
                sacc[j][rr*2] = p0; sacc[j][rr*2+1] = p1;
                ls += p0 + p1;
            }
            ls += __shfl_xor_sync(0xffffffffu, ls, 1);
            ls += __shfl_xor_sync(0xffffffffu, ls, 2);
            lrow[rr] = lrow[rr] * alpha + ls;
            mrow[rr] = mn;
#pragma unroll
            for (int j = 0; j < 16; j++) {
                oacc[j][rr*2]   *= alpha;
                oacc[j][rr*2+1] *= alpha;
            }
        }

        // ---- O += P·V (1-pass, P unsplit); V frags double-buffered ----
#pragma unroll
        for (int ks = 0; ks < 4; ks++) {
            uint32_t pa[4];
#pragma unroll
            for (int half = 0; half < 2; half++) {
                const float* sc = sacc[2*ks + half];
                pa[2*half]   = pack_h2(sc[0], sc[1]);
                pa[2*half+1] = pack_h2(sc[2], sc[3]);
            }
            uint32_t vba[4], vbb[4];
            ldsm4t(vba, s + AKV_K + swz(ks * 16 + vrow_off, vb_off));
#pragma unroll
            for (int jp = 0; jp < 8; jp++) {
                const uint32_t* cur = (jp & 1) ? vbb : vba;
                if (jp < 7)
                    ldsm4t((jp & 1) ? vba : vbb,
                           s + AKV_K + swz(ks * 16 + vrow_off, (jp + 1) * 32 + vb_off));
                mma_f16(oacc[2*jp],   pa, &cur[0]);
                mma_f16(oacc[2*jp+1], pa, &cur[2]);
            }
        }
        __syncthreads();
    }

    // ---- Epilogue: normalize, write single fp16 [b,t,h*128+hd] ----
    const int b_ = bh >> 4, h_ = bh & 15;
    const float inv0 = 1.0f / lrow[0], inv1 = 1.0f / lrow[1];
#pragma unroll
    for (int rr = 0; rr < 2; rr++) {
        const int t = q0 + wid * 16 + (lane >> 2) + rr * 8;
        const size_t base = ((size_t)(b_ * SEQ + t)) * EMBED + h_ * HDIM;
        const float inv = rr ? inv1 : inv0;
#pragma unroll
        for (int j = 0; j < 16; j++) {
            const int hd = j * 8 + (lane & 3) * 2;
            *(uint32_t*)(g_A + base + hd) =
                pack_h2(oacc[j][rr*2] * inv, oacc[j][rr*2+1] * inv);
        }
    }
}

// ---------------------------------------------------------------------------
// Launch sequence
// ---------------------------------------------------------------------------
#define GEMM_SMEM1 (4 * 2 * G_ARR)   // 65536
#define GEMM_SMEM2 (4 * 3 * G_ARR)   // 98304

extern "C" void kernel_launch(void* const* d_in, const int* in_sizes, int n_in,
                              void* d_out, int out_size)
{
    (void)in_sizes; (void)n_in; (void)out_size;
    const float* x  = (const float*)d_in[0];
    const float* wq = (const float*)d_in[1];
    const float* bq = (const float*)d_in[2];
    const float* wk = (const float*)d_in[3];
    const float* bk = (const float*)d_in[4];
    const float* wv = (const float*)d_in[5];
    const float* bv = (const float*)d_in[6];
    const float* wo = (const float*)d_in[7];
    const float* bo = (const float*)d_in[8];
    float* out = (float*)d_out;

    cudaFuncSetAttribute(qkv_mma_kernel,
                         cudaFuncAttributeMaxDynamicSharedMemorySize, GEMM_SMEM1);
    cudaFuncSetAttribute(o_mma_kernel,
                         cudaFuncAttributeMaxDynamicSharedMemorySize, GEMM_SMEM2);
    cudaFuncSetAttribute(attn_mma_kernel,
                         cudaFuncAttributeMaxDynamicSharedMemorySize, AT_SMEM);

    // 1. convert x -> fp16
    cvt_kernel<<<(NTOK * EMBED / 4) / 256, 256>>>(x);
    // 2. transpose + split weights (fp16 hi/lo)
    wsplit_kernel<<<dim3(EMBED / 32, EMBED / 32, 4), dim3(32, 8)>>>(wq, wk, wv, wo);
    // 3. Q,K,V projections (fused, 1-pass)
    qkv_mma_kernel<<<dim3(16, 32, 3), 256, GEMM_SMEM1>>>(bq, bk, bv);
    // 4. tensor-core flash attention -> fp16 A
    attn_mma_kernel<<<dim3(SEQ / 64, BATCH * NHEAD), 128, AT_SMEM>>>();
    // 5. output projection (2-pass) -> fp32 out
    o_mma_kernel<<<dim3(16, 32), 256, GEMM_SMEM2>>>(bo, out);
}